// round 12
// baseline (speedup 1.0000x reference)
#include <cuda_runtime.h>
#include <cstdint>

typedef unsigned long long ull;

#define NEXPERTS 64
#define S_MAX    8192
#define ZCHUNK   16384      // bytes per bulk store (= smem zero buffer size)
#define NZEXTRA  64         // pure zero blocks (STG warps + a TMA issuer each)

// static scratch (no allocations allowed)
__device__ int   g_idx[S_MAX];
__device__ float g_gate[S_MAX];
__device__ float g_me_partial[(S_MAX / 64) * NEXPERTS];  // per-gemm-block gate sums
__device__ int   g_cnt[(S_MAX / 512) * NEXPERTS];        // per-chunk expert counts
__device__ int   g_base[(S_MAX / 512) * NEXPERTS];       // exclusive prefix per chunk
__device__ int   g_rank[S_MAX];                          // rank within chunk
__device__ float g_prod[NEXPERTS];                       // me*ce per expert

__device__ __forceinline__ ull pack2(float lo, float hi) {
    ull r; asm("mov.b64 %0, {%1, %2};" : "=l"(r) : "f"(lo), "f"(hi)); return r;
}
__device__ __forceinline__ void ffma2(ull& d, ull a, ull b) {
    asm("fma.rn.f32x2 %0, %1, %2, %0;" : "+l"(d) : "l"(a), "l"(b));
}
__device__ __forceinline__ void fadd2(ull& d, ull a) {
    asm("add.rn.f32x2 %0, %0, %1;" : "+l"(d) : "l"(a));
}
__device__ __forceinline__ float2 unpack2(ull v) {
    float2 r; asm("mov.b64 {%0, %1}, %2;" : "=f"(r.x), "=f"(r.y) : "l"(v)); return r;
}
__device__ __forceinline__ uint32_t smem_u32(const void* p) {
    uint32_t a;
    asm("{ .reg .u64 t; cvta.to.shared.u64 t, %1; cvt.u32.u64 %0, t; }" : "=r"(a) : "l"(p));
    return a;
}
// named barrier for the 8 gemm warps only (TMA warp never joins)
#define GSYNC() asm volatile("bar.sync 1, 256;" ::: "memory")

__device__ __forceinline__ void stg_zero_range(float4* base, size_t n4,
                                               size_t start, size_t stride) {
    const float4 z = make_float4(0.f, 0.f, 0.f, 0.f);
    size_t i = start;
    for (; i + 3 * stride < n4; i += 4 * stride) {
        base[i]              = z;
        base[i + stride]     = z;
        base[i + 2 * stride] = z;
        base[i + 3 * stride] = z;
    }
    for (; i < n4; i += stride) base[i] = z;
}

// ---------------------------------------------------------------------------
// Kernel 1 (warp-specialized, hybrid dual-path zeroing): 288 threads,
// grid = ngemm + NZEXTRA blocks. d_out is split into three zones:
//   zone T [0, tmaB):            TMA bulk stores, issued by warp 8 of EVERY
//                                block (chunk-strided). No SM issue slots.
//   zone P [tmaB, tmaB+pureB):   STG.128 streams from the 8 idle gemm warps
//                                of the NZEXTRA pure blocks, starting at t=0.
//   zone G [tmaB+pureB, end):    STG.128 from the 128 gemm blocks' 8 warps
//                                AFTER their gemm+softmax epilogue (~60us in).
// TMA (dedicated engine, ~4.3 TB/s ceiling observed in R10/R11) and LSU-STG
// (5.7 TB/s observed in R6) are independent store paths; combined they
// approach the LTS cap while the fma-bound gemm runs beneath.
// ---------------------------------------------------------------------------
__global__ __launch_bounds__(288) void gemm_zero_softmax(const float* __restrict__ x,
                                                         const float* __restrict__ wg,
                                                         int D, int S, int ngemm,
                                                         char* __restrict__ zout,
                                                         size_t zbytes,
                                                         size_t tmaB, size_t pureB) {
    __shared__ __align__(16) float sm[64 * 68];     // As[32][68]+Bs[32][68] -> Ls[64][68]
    __shared__ __align__(16) ull  partial[128][16]; // k-split partial accumulators
    __shared__ __align__(128) float4 zbuf[ZCHUNK / 16];
    __shared__ float sm_m[64], sm_inv[64], red4[4][64];
    float (*As)[68] = (float(*)[68])sm;
    float (*Bs)[68] = (float(*)[68])(sm + 32 * 68);
    float (*Ls)[68] = (float(*)[68])sm;

    const int tid = threadIdx.x;
    const int bid = blockIdx.x;
    const size_t n16 = zbytes & ~(size_t)15;

    if (tid >= 256) {
        // ---------------- TMA zero warp (all blocks): zone T ----------------
        const int lane = tid - 256;
        const float4 z4 = make_float4(0.f, 0.f, 0.f, 0.f);
        for (int i = lane; i < ZCHUNK / 16; i += 32) zbuf[i] = z4;
        asm volatile("fence.proxy.async.shared::cta;" ::: "memory");
        __syncwarp();

        if (lane == 0) {
            const uint32_t saddr = smem_u32(zbuf);
            const size_t nchunk = (tmaB + ZCHUNK - 1) / ZCHUNK;
            for (size_t c = bid; c < nchunk; c += gridDim.x) {
                size_t off = c * (size_t)ZCHUNK;
                uint32_t sz = (uint32_t)((tmaB - off < ZCHUNK) ? (tmaB - off) : ZCHUNK);
                asm volatile(
                    "cp.async.bulk.global.shared::cta.bulk_group [%0], [%1], %2;"
                    :: "l"(zout + off), "r"(saddr), "r"(sz) : "memory");
            }
            asm volatile("cp.async.bulk.commit_group;" ::: "memory");
            asm volatile("cp.async.bulk.wait_group 0;" ::: "memory");
            if (bid == 0) {                        // tail bytes (< 16)
                for (size_t t = n16; t < zbytes; t += 4) *(float*)(zout + t) = 0.f;
            }
        }
        return;   // never touches named barrier 1
    }

    if (bid >= ngemm) {
        // ------------- pure zero block: STG stream over zone P -------------
        stg_zero_range((float4*)(zout + tmaB), pureB / 16,
                       (size_t)(bid - ngemm) * 256 + tid, (size_t)NZEXTRA * 256);
        return;
    }

    // ---------------- GEMM warps (tid 0..255) ----------------
    const int g    = tid >> 7;         // k-split half
    const int tid2 = tid & 127;
    const int ty   = tid2 >> 4;        // 0..7  -> tokens ty*8 .. ty*8+7
    const int tx   = tid2 & 15;        // 0..15 -> experts tx*4 .. tx*4+3
    const int s0   = bid * 64;

    int rowr[2], k4r[2];
    const float *xp[2], *wp[2];
#pragma unroll
    for (int r = 0; r < 2; ++r) {
        int i = tid + r * 256;
        rowr[r] = i >> 3; k4r[r] = (i & 7) << 2;
        xp[r] = x  + (size_t)(s0 + rowr[r]) * D + k4r[r];
        wp[r] = wg + (size_t)rowr[r] * D + k4r[r];
    }

    ull acc[4][4];
#pragma unroll
    for (int i = 0; i < 4; ++i)
#pragma unroll
        for (int j = 0; j < 4; ++j) acc[i][j] = 0ull;

    float4 pa[2], pb[2];
#pragma unroll
    for (int r = 0; r < 2; ++r) { pa[r] = *(const float4*)(xp[r]); pb[r] = *(const float4*)(wp[r]); }

    for (int kt = 0; kt < D; kt += 32) {
#pragma unroll
        for (int r = 0; r < 2; ++r) {
            int row = rowr[r], k4 = k4r[r];
            As[k4 + 0][row] = pa[r].x; As[k4 + 1][row] = pa[r].y;
            As[k4 + 2][row] = pa[r].z; As[k4 + 3][row] = pa[r].w;
            Bs[k4 + 0][row] = pb[r].x; Bs[k4 + 1][row] = pb[r].y;
            Bs[k4 + 2][row] = pb[r].z; Bs[k4 + 3][row] = pb[r].w;
        }
        GSYNC();
        if (kt + 32 < D) {
#pragma unroll
            for (int r = 0; r < 2; ++r) {
                pa[r] = *(const float4*)(xp[r] + kt + 32);
                pb[r] = *(const float4*)(wp[r] + kt + 32);
            }
        }
#pragma unroll
        for (int k = 0; k < 16; ++k) {
            const int kk = k + g * 16;
            ulonglong2 A0 = *(const ulonglong2*)&As[kk][ty * 8];
            ulonglong2 A1 = *(const ulonglong2*)&As[kk][ty * 8 + 4];
            ull a0 = A0.x, a1 = A0.y, a2 = A1.x, a3 = A1.y;   // 8 tokens (4 pairs)
            float4 bv = *(const float4*)&Bs[kk][tx * 4];
            ull b0 = pack2(bv.x, bv.x), b1 = pack2(bv.y, bv.y);
            ull b2 = pack2(bv.z, bv.z), b3 = pack2(bv.w, bv.w);
            ffma2(acc[0][0], a0, b0); ffma2(acc[0][1], a0, b1);
            ffma2(acc[0][2], a0, b2); ffma2(acc[0][3], a0, b3);
            ffma2(acc[1][0], a1, b0); ffma2(acc[1][1], a1, b1);
            ffma2(acc[1][2], a1, b2); ffma2(acc[1][3], a1, b3);
            ffma2(acc[2][0], a2, b0); ffma2(acc[2][1], a2, b1);
            ffma2(acc[2][2], a2, b2); ffma2(acc[2][3], a2, b3);
            ffma2(acc[3][0], a3, b0); ffma2(acc[3][1], a3, b1);
            ffma2(acc[3][2], a3, b2); ffma2(acc[3][3], a3, b3);
        }
        GSYNC();
    }

    // k-split reduce: half g=1 parks partials in smem, half g=0 accumulates
    if (g == 1) {
#pragma unroll
        for (int i = 0; i < 4; ++i)
#pragma unroll
            for (int j = 0; j < 4; ++j)
                partial[tid2][i * 4 + j] = acc[i][j];
    }
    GSYNC();
    if (g == 0) {
#pragma unroll
        for (int i = 0; i < 4; ++i)
#pragma unroll
            for (int j = 0; j < 4; ++j)
                fadd2(acc[i][j], partial[tid2][i * 4 + j]);
    }
    GSYNC();

    // dump logit tile into smem (As/Bs dead now)
    if (g == 0) {
#pragma unroll
        for (int i = 0; i < 4; ++i) {
            float2 c0 = unpack2(acc[i][0]);
            float2 c1 = unpack2(acc[i][1]);
            float2 c2 = unpack2(acc[i][2]);
            float2 c3 = unpack2(acc[i][3]);
            int t0 = ty * 8 + 2 * i;
            *(float4*)&Ls[t0][tx * 4]     = make_float4(c0.x, c1.x, c2.x, c3.x);
            *(float4*)&Ls[t0 + 1][tx * 4] = make_float4(c0.y, c1.y, c2.y, c3.y);
        }
    }
    GSYNC();

    // per-token softmax + argmax (first max wins = jnp.argmax)
    if (tid < 64) {
        float m = -1e30f; int ix = 0;
#pragma unroll 8
        for (int e = 0; e < 64; ++e) {
            float v = Ls[tid][e];
            if (v > m) { m = v; ix = e; }
        }
        float ssum = 0.f;
#pragma unroll 8
        for (int e = 0; e < 64; ++e) ssum += expf(Ls[tid][e] - m);
        float inv = 1.0f / ssum;
        g_idx[s0 + tid]  = ix;
        g_gate[s0 + tid] = inv;
        sm_m[tid] = m; sm_inv[tid] = inv;
    }
    GSYNC();

    // per-block me partials: me_e += sum_t softmax(l)[t][e]
    {
        const int e = tid & 63, q = tid >> 6;     // q: 0..3, 16 tokens each
        float mp = 0.f;
#pragma unroll
        for (int t = q * 16; t < q * 16 + 16; ++t)
            mp += expf(Ls[t][e] - sm_m[t]) * sm_inv[t];
        red4[q][e] = mp;
    }
    GSYNC();
    if (tid < 64)
        g_me_partial[(size_t)bid * 64 + tid] =
            red4[0][tid] + red4[1][tid] + red4[2][tid] + red4[3][tid];

    // ------------- post-epilogue: gemm warps STG-zero zone G -------------
    {
        const size_t gB = n16 - tmaB - pureB;
        stg_zero_range((float4*)(zout + tmaB + pureB), gB / 16,
                       (size_t)bid * 256 + tid, (size_t)ngemm * 256);
    }
}

// ---------------------------------------------------------------------------
// Kernel 2: per-512-token chunk: warp-ballot ranks + per-chunk expert counts.
// ---------------------------------------------------------------------------
__global__ __launch_bounds__(512) void hist_rank() {
    __shared__ int hist[16][64];
    const int tid  = threadIdx.x;
    const int lane = tid & 31;
    const int warp = tid >> 5;
    const int s = blockIdx.x * 512 + tid;

    hist[tid >> 6][tid & 63] = 0;
    ((int*)hist)[512 + tid] = 0;
    __syncthreads();

    const int e = g_idx[s];
    unsigned mask = __match_any_sync(0xffffffffu, e);
    int inrank = __popc(mask & ((1u << lane) - 1));
    int cnt    = __popc(mask);
    if (inrank == 0) hist[warp][e] = cnt;
    __syncthreads();

    if (tid < 64) {
        int run = 0;
#pragma unroll
        for (int w = 0; w < 16; ++w) {
            int t = hist[w][tid]; hist[w][tid] = run; run += t;
        }
        g_cnt[blockIdx.x * 64 + tid] = run;
    }
    __syncthreads();
    g_rank[s] = hist[warp][e] + inrank;
}

// ---------------------------------------------------------------------------
// Kernel 3: per-expert prefix + me reduction (64 blocks, one per expert).
// Deterministic: fixed tree order within a block, fixed chunk order.
// ---------------------------------------------------------------------------
__global__ __launch_bounds__(128) void prefix64(int S, int nblk, int nchunks) {
    __shared__ float red[128];
    const int e = blockIdx.x;
    const int t = threadIdx.x;

    float mp = 0.f;
    for (int b = t; b < nblk; b += 128) mp += g_me_partial[(size_t)b * 64 + e];
    red[t] = mp;
    __syncthreads();
#pragma unroll
    for (int o = 64; o; o >>= 1) {
        if (t < o) red[t] += red[t + o];
        __syncthreads();
    }
    if (t == 0) {
        int run = 0;
        for (int c = 0; c < nchunks; ++c) {
            int v = g_cnt[c * 64 + e];
            g_base[c * 64 + e] = run;
            run += v;
        }
        float me = red[0] / (float)S;
        float ce = (float)run / (float)S;   // counts BEFORE capacity drop
        g_prod[e] = me * ce;
    }
}

// ---------------------------------------------------------------------------
// Kernel 4: sparse scatter into the (zeroed) output + l_aux (block 0,
// fixed-order serial sum -> deterministic).
// ---------------------------------------------------------------------------
__global__ void scatter_out(float* __restrict__ out, int S, int C,
                            long long comb_off, long long disp_off, int write_aux) {
    if (blockIdx.x == 0) {
        __shared__ float pr[64];
        if (threadIdx.x < 64) pr[threadIdx.x] = g_prod[threadIdx.x];
        __syncthreads();
        if (threadIdx.x == 0 && write_aux) {
            float sum = 0.f;
            for (int e2 = 0; e2 < 64; ++e2) sum += pr[e2];
            out[0] = sum * (float)NEXPERTS;   // mean(me*ce)*E^2 = sum*E
        }
    }
    int s = blockIdx.x * blockDim.x + threadIdx.x;
    if (s < S) {
        int e = g_idx[s];
        int r = g_base[(s >> 9) * 64 + e] + g_rank[s];
        if (r < C) {
            size_t pos = ((size_t)s * NEXPERTS + e) * (size_t)C + r;
            out[(size_t)comb_off + pos] = g_gate[s];
            if (disp_off >= 0)
                out[(size_t)disp_off + pos] = 1.0f;
        }
    }
}

extern "C" void kernel_launch(void* const* d_in, const int* in_sizes, int n_in,
                              void* d_out, int out_size) {
    const float* x  = (const float*)d_in[0];
    const float* wg = (const float*)d_in[1];
    const int D = in_sizes[1] / NEXPERTS;
    const int S = in_sizes[0] / D;
    const int C = (S + NEXPERTS - 1) / NEXPERTS;   // capacity_factor = 1.0
    const size_t SEC = (size_t)S * NEXPERTS * C;
    const size_t osz = (size_t)out_size;

    long long comb = 0, disp = -1; int aux = 0;
    if (osz >= 2 * SEC + 1)      { aux = 1; comb = 1; disp = 1 + (long long)SEC; }
    else if (osz >= 2 * SEC)     { comb = 0; disp = (long long)SEC; }

    const int ngemm = S / 64;
    const size_t zbytes = osz * sizeof(float);
    const size_t n16 = zbytes & ~(size_t)15;
    size_t tmaB  = (n16 / 2) & ~(size_t)15;                 // 50% via TMA engines
    size_t pureB = (n16 * 3 / 10) & ~(size_t)15;            // 30% via pure-block STG
    if (tmaB + pureB > n16) pureB = n16 - tmaB;             // (zone G gets the rest)

    gemm_zero_softmax<<<ngemm + NZEXTRA, 288>>>(x, wg, D, S, ngemm,
                                                (char*)d_out, zbytes, tmaB, pureB);
    hist_rank<<<S / 512, 512>>>();
    prefix64<<<NEXPERTS, 128>>>(S, ngemm, S / 512);
    scatter_out<<<(S + 255) / 256, 256>>>((float*)d_out, S, C, comb, disp, aux);
}

// round 13
// speedup vs baseline: 1.2351x; 1.2351x over previous
#include <cuda_runtime.h>
#include <cstdint>

typedef unsigned long long ull;

#define NEXPERTS 64
#define S_MAX    8192
#define ZCHUNK   16384      // bytes per bulk store (= smem zero buffer size)

// static scratch (no allocations allowed)
__device__ int   g_idx[S_MAX];
__device__ float g_gate[S_MAX];
__device__ float g_me_partial[(S_MAX / 64) * NEXPERTS];  // per-gemm-block gate sums
__device__ int   g_cnt[(S_MAX / 512) * NEXPERTS];        // per-chunk expert counts
__device__ int   g_base[(S_MAX / 512) * NEXPERTS];       // exclusive prefix per chunk
__device__ int   g_rank[S_MAX];                          // rank within chunk
__device__ float g_prod[NEXPERTS];                       // me*ce per expert

__device__ __forceinline__ ull pack2(float lo, float hi) {
    ull r; asm("mov.b64 %0, {%1, %2};" : "=l"(r) : "f"(lo), "f"(hi)); return r;
}
__device__ __forceinline__ void ffma2(ull& d, ull a, ull b) {
    asm("fma.rn.f32x2 %0, %1, %2, %0;" : "+l"(d) : "l"(a), "l"(b));
}
__device__ __forceinline__ void fadd2(ull& d, ull a) {
    asm("add.rn.f32x2 %0, %0, %1;" : "+l"(d) : "l"(a));
}
__device__ __forceinline__ float2 unpack2(ull v) {
    float2 r; asm("mov.b64 {%0, %1}, %2;" : "=f"(r.x), "=f"(r.y) : "l"(v)); return r;
}
__device__ __forceinline__ uint32_t smem_u32(const void* p) {
    uint32_t a;
    asm("{ .reg .u64 t; cvta.to.shared.u64 t, %1; cvt.u32.u64 %0, t; }" : "=r"(a) : "l"(p));
    return a;
}
// named barrier for the 8 gemm warps only (TMA warp never joins)
#define GSYNC() asm volatile("bar.sync 1, 256;" ::: "memory")

__device__ __forceinline__ void stg_zero_range(float4* base, size_t n4,
                                               size_t start, size_t stride) {
    const float4 z = make_float4(0.f, 0.f, 0.f, 0.f);
    size_t i = start;
    for (; i + 3 * stride < n4; i += 4 * stride) {
        base[i]              = z;
        base[i + stride]     = z;
        base[i + 2 * stride] = z;
        base[i + 3 * stride] = z;
    }
    for (; i < n4; i += stride) base[i] = z;
}

// ---------------------------------------------------------------------------
// Kernel 1 (warp-specialized): 288 threads, grid = ngemm (=128) blocks.
//   warps 0-7: gemm+softmax for one 64-token tile (2-way k-split, micro
//     8 tok x 4 exp, FFMA2, named-barrier synced). AFTER the epilogue
//     (~60us in, SMs otherwise idle) they STG-stream zone G of d_out.
//   warp 8: TMA bulk zero-stores over zone T (84% of d_out), chunk-strided
//     across blocks. TMA costs no SM issue slots -> overlaps the gemm fully.
// Zone split sized so both drains finish together (~105us):
//   TMA path ceiling measured ~4.3 TB/s (R10/R11); STG joins only after the
//   gemm is done (R12 lesson: concurrent STG blocks thrash the gemm).
// ---------------------------------------------------------------------------
__global__ __launch_bounds__(288) void gemm_zero_softmax(const float* __restrict__ x,
                                                         const float* __restrict__ wg,
                                                         int D, int S, int ngemm,
                                                         char* __restrict__ zout,
                                                         size_t zbytes, size_t tmaB) {
    __shared__ __align__(16) float sm[64 * 68];     // As[32][68]+Bs[32][68] -> Ls[64][68]
    __shared__ __align__(16) ull  partial[128][16]; // k-split partial accumulators
    __shared__ __align__(128) float4 zbuf[ZCHUNK / 16];
    __shared__ float sm_m[64], sm_inv[64], red4[4][64];
    float (*As)[68] = (float(*)[68])sm;
    float (*Bs)[68] = (float(*)[68])(sm + 32 * 68);
    float (*Ls)[68] = (float(*)[68])sm;

    const int tid = threadIdx.x;
    const int bid = blockIdx.x;
    const size_t n16 = zbytes & ~(size_t)15;

    if (tid >= 256) {
        // ---------------- TMA zero warp: zone T [0, tmaB) ----------------
        const int lane = tid - 256;
        const float4 z4 = make_float4(0.f, 0.f, 0.f, 0.f);
        for (int i = lane; i < ZCHUNK / 16; i += 32) zbuf[i] = z4;
        asm volatile("fence.proxy.async.shared::cta;" ::: "memory");
        __syncwarp();

        if (lane == 0) {
            const uint32_t saddr = smem_u32(zbuf);
            const size_t nchunk = (tmaB + ZCHUNK - 1) / ZCHUNK;
            for (size_t c = bid; c < nchunk; c += gridDim.x) {
                size_t off = c * (size_t)ZCHUNK;
                uint32_t sz = (uint32_t)((tmaB - off < ZCHUNK) ? (tmaB - off) : ZCHUNK);
                asm volatile(
                    "cp.async.bulk.global.shared::cta.bulk_group [%0], [%1], %2;"
                    :: "l"(zout + off), "r"(saddr), "r"(sz) : "memory");
            }
            asm volatile("cp.async.bulk.commit_group;" ::: "memory");
            asm volatile("cp.async.bulk.wait_group 0;" ::: "memory");
            if (bid == 0) {                        // tail bytes (< 16)
                for (size_t t = n16; t < zbytes; t += 4) *(float*)(zout + t) = 0.f;
            }
        }
        return;   // never touches named barrier 1
    }

    // ---------------- GEMM warps (tid 0..255) ----------------
    const int g    = tid >> 7;         // k-split half
    const int tid2 = tid & 127;
    const int ty   = tid2 >> 4;        // 0..7  -> tokens ty*8 .. ty*8+7
    const int tx   = tid2 & 15;        // 0..15 -> experts tx*4 .. tx*4+3
    const int s0   = bid * 64;

    int rowr[2], k4r[2];
    const float *xp[2], *wp[2];
#pragma unroll
    for (int r = 0; r < 2; ++r) {
        int i = tid + r * 256;
        rowr[r] = i >> 3; k4r[r] = (i & 7) << 2;
        xp[r] = x  + (size_t)(s0 + rowr[r]) * D + k4r[r];
        wp[r] = wg + (size_t)rowr[r] * D + k4r[r];
    }

    ull acc[4][4];
#pragma unroll
    for (int i = 0; i < 4; ++i)
#pragma unroll
        for (int j = 0; j < 4; ++j) acc[i][j] = 0ull;

    float4 pa[2], pb[2];
#pragma unroll
    for (int r = 0; r < 2; ++r) { pa[r] = *(const float4*)(xp[r]); pb[r] = *(const float4*)(wp[r]); }

    for (int kt = 0; kt < D; kt += 32) {
#pragma unroll
        for (int r = 0; r < 2; ++r) {
            int row = rowr[r], k4 = k4r[r];
            As[k4 + 0][row] = pa[r].x; As[k4 + 1][row] = pa[r].y;
            As[k4 + 2][row] = pa[r].z; As[k4 + 3][row] = pa[r].w;
            Bs[k4 + 0][row] = pb[r].x; Bs[k4 + 1][row] = pb[r].y;
            Bs[k4 + 2][row] = pb[r].z; Bs[k4 + 3][row] = pb[r].w;
        }
        GSYNC();
        if (kt + 32 < D) {
#pragma unroll
            for (int r = 0; r < 2; ++r) {
                pa[r] = *(const float4*)(xp[r] + kt + 32);
                pb[r] = *(const float4*)(wp[r] + kt + 32);
            }
        }
#pragma unroll
        for (int k = 0; k < 16; ++k) {
            const int kk = k + g * 16;
            ulonglong2 A0 = *(const ulonglong2*)&As[kk][ty * 8];
            ulonglong2 A1 = *(const ulonglong2*)&As[kk][ty * 8 + 4];
            ull a0 = A0.x, a1 = A0.y, a2 = A1.x, a3 = A1.y;   // 8 tokens (4 pairs)
            float4 bv = *(const float4*)&Bs[kk][tx * 4];
            ull b0 = pack2(bv.x, bv.x), b1 = pack2(bv.y, bv.y);
            ull b2 = pack2(bv.z, bv.z), b3 = pack2(bv.w, bv.w);
            ffma2(acc[0][0], a0, b0); ffma2(acc[0][1], a0, b1);
            ffma2(acc[0][2], a0, b2); ffma2(acc[0][3], a0, b3);
            ffma2(acc[1][0], a1, b0); ffma2(acc[1][1], a1, b1);
            ffma2(acc[1][2], a1, b2); ffma2(acc[1][3], a1, b3);
            ffma2(acc[2][0], a2, b0); ffma2(acc[2][1], a2, b1);
            ffma2(acc[2][2], a2, b2); ffma2(acc[2][3], a2, b3);
            ffma2(acc[3][0], a3, b0); ffma2(acc[3][1], a3, b1);
            ffma2(acc[3][2], a3, b2); ffma2(acc[3][3], a3, b3);
        }
        GSYNC();
    }

    // k-split reduce: half g=1 parks partials in smem, half g=0 accumulates
    if (g == 1) {
#pragma unroll
        for (int i = 0; i < 4; ++i)
#pragma unroll
            for (int j = 0; j < 4; ++j)
                partial[tid2][i * 4 + j] = acc[i][j];
    }
    GSYNC();
    if (g == 0) {
#pragma unroll
        for (int i = 0; i < 4; ++i)
#pragma unroll
            for (int j = 0; j < 4; ++j)
                fadd2(acc[i][j], partial[tid2][i * 4 + j]);
    }
    GSYNC();

    // dump logit tile into smem (As/Bs dead now)
    if (g == 0) {
#pragma unroll
        for (int i = 0; i < 4; ++i) {
            float2 c0 = unpack2(acc[i][0]);
            float2 c1 = unpack2(acc[i][1]);
            float2 c2 = unpack2(acc[i][2]);
            float2 c3 = unpack2(acc[i][3]);
            int t0 = ty * 8 + 2 * i;
            *(float4*)&Ls[t0][tx * 4]     = make_float4(c0.x, c1.x, c2.x, c3.x);
            *(float4*)&Ls[t0 + 1][tx * 4] = make_float4(c0.y, c1.y, c2.y, c3.y);
        }
    }
    GSYNC();

    // per-token softmax + argmax (first max wins = jnp.argmax)
    if (tid < 64) {
        float m = -1e30f; int ix = 0;
#pragma unroll 8
        for (int e = 0; e < 64; ++e) {
            float v = Ls[tid][e];
            if (v > m) { m = v; ix = e; }
        }
        float ssum = 0.f;
#pragma unroll 8
        for (int e = 0; e < 64; ++e) ssum += expf(Ls[tid][e] - m);
        float inv = 1.0f / ssum;
        g_idx[s0 + tid]  = ix;
        g_gate[s0 + tid] = inv;
        sm_m[tid] = m; sm_inv[tid] = inv;
    }
    GSYNC();

    // per-block me partials: me_e += sum_t softmax(l)[t][e]
    {
        const int e = tid & 63, q = tid >> 6;     // q: 0..3, 16 tokens each
        float mp = 0.f;
#pragma unroll
        for (int t = q * 16; t < q * 16 + 16; ++t)
            mp += expf(Ls[t][e] - sm_m[t]) * sm_inv[t];
        red4[q][e] = mp;
    }
    GSYNC();
    if (tid < 64)
        g_me_partial[(size_t)bid * 64 + tid] =
            red4[0][tid] + red4[1][tid] + red4[2][tid] + red4[3][tid];

    // ---- post-epilogue: gemm warps STG-zero zone G [tmaB, n16) ----
    // SMs are idle of fma work now; no contention with the (ongoing) TMA drain.
    stg_zero_range((float4*)(zout + tmaB), (n16 - tmaB) / 16,
                   (size_t)bid * 256 + tid, (size_t)ngemm * 256);
}

// ---------------------------------------------------------------------------
// Kernel 2: per-512-token chunk: warp-ballot ranks + per-chunk expert counts.
// ---------------------------------------------------------------------------
__global__ __launch_bounds__(512) void hist_rank() {
    __shared__ int hist[16][64];
    const int tid  = threadIdx.x;
    const int lane = tid & 31;
    const int warp = tid >> 5;
    const int s = blockIdx.x * 512 + tid;

    hist[tid >> 6][tid & 63] = 0;
    ((int*)hist)[512 + tid] = 0;
    __syncthreads();

    const int e = g_idx[s];
    unsigned mask = __match_any_sync(0xffffffffu, e);
    int inrank = __popc(mask & ((1u << lane) - 1));
    int cnt    = __popc(mask);
    if (inrank == 0) hist[warp][e] = cnt;
    __syncthreads();

    if (tid < 64) {
        int run = 0;
#pragma unroll
        for (int w = 0; w < 16; ++w) {
            int t = hist[w][tid]; hist[w][tid] = run; run += t;
        }
        g_cnt[blockIdx.x * 64 + tid] = run;
    }
    __syncthreads();
    g_rank[s] = hist[warp][e] + inrank;
}

// ---------------------------------------------------------------------------
// Kernel 3: per-expert prefix + me reduction (64 blocks, one per expert).
// Deterministic: fixed tree order within a block, fixed chunk order.
// ---------------------------------------------------------------------------
__global__ __launch_bounds__(128) void prefix64(int S, int nblk, int nchunks) {
    __shared__ float red[128];
    const int e = blockIdx.x;
    const int t = threadIdx.x;

    float mp = 0.f;
    for (int b = t; b < nblk; b += 128) mp += g_me_partial[(size_t)b * 64 + e];
    red[t] = mp;
    __syncthreads();
#pragma unroll
    for (int o = 64; o; o >>= 1) {
        if (t < o) red[t] += red[t + o];
        __syncthreads();
    }
    if (t == 0) {
        int run = 0;
        for (int c = 0; c < nchunks; ++c) {
            int v = g_cnt[c * 64 + e];
            g_base[c * 64 + e] = run;
            run += v;
        }
        float me = red[0] / (float)S;
        float ce = (float)run / (float)S;   // counts BEFORE capacity drop
        g_prod[e] = me * ce;
    }
}

// ---------------------------------------------------------------------------
// Kernel 4: sparse scatter into the (zeroed) output + l_aux (block 0,
// fixed-order serial sum -> deterministic).
// ---------------------------------------------------------------------------
__global__ void scatter_out(float* __restrict__ out, int S, int C,
                            long long comb_off, long long disp_off, int write_aux) {
    if (blockIdx.x == 0) {
        __shared__ float pr[64];
        if (threadIdx.x < 64) pr[threadIdx.x] = g_prod[threadIdx.x];
        __syncthreads();
        if (threadIdx.x == 0 && write_aux) {
            float sum = 0.f;
            for (int e2 = 0; e2 < 64; ++e2) sum += pr[e2];
            out[0] = sum * (float)NEXPERTS;   // mean(me*ce)*E^2 = sum*E
        }
    }
    int s = blockIdx.x * blockDim.x + threadIdx.x;
    if (s < S) {
        int e = g_idx[s];
        int r = g_base[(s >> 9) * 64 + e] + g_rank[s];
        if (r < C) {
            size_t pos = ((size_t)s * NEXPERTS + e) * (size_t)C + r;
            out[(size_t)comb_off + pos] = g_gate[s];
            if (disp_off >= 0)
                out[(size_t)disp_off + pos] = 1.0f;
        }
    }
}

extern "C" void kernel_launch(void* const* d_in, const int* in_sizes, int n_in,
                              void* d_out, int out_size) {
    const float* x  = (const float*)d_in[0];
    const float* wg = (const float*)d_in[1];
    const int D = in_sizes[1] / NEXPERTS;
    const int S = in_sizes[0] / D;
    const int C = (S + NEXPERTS - 1) / NEXPERTS;   // capacity_factor = 1.0
    const size_t SEC = (size_t)S * NEXPERTS * C;
    const size_t osz = (size_t)out_size;

    long long comb = 0, disp = -1; int aux = 0;
    if (osz >= 2 * SEC + 1)      { aux = 1; comb = 1; disp = 1 + (long long)SEC; }
    else if (osz >= 2 * SEC)     { comb = 0; disp = (long long)SEC; }

    const int ngemm = S / 64;
    const size_t zbytes = osz * sizeof(float);
    const size_t n16 = zbytes & ~(size_t)15;
    // zone T (TMA) = 84%; zone G (post-gemm STG) = 16%, sized so both drains
    // finish together given TMA ~4.3 TB/s and gemm end ~60-65us.
    size_t tmaB = (n16 * 84 / 100) & ~(size_t)15;

    gemm_zero_softmax<<<ngemm, 288>>>(x, wg, D, S, ngemm,
                                      (char*)d_out, zbytes, tmaB);
    hist_rank<<<S / 512, 512>>>();
    prefix64<<<NEXPERTS, 128>>>(S, ngemm, S / 512);
    scatter_out<<<(S + 255) / 256, 256>>>((float*)d_out, S, C, comb, disp, aux);
}

// round 14
// speedup vs baseline: 1.3287x; 1.0758x over previous
#include <cuda_runtime.h>
#include <cstdint>

typedef unsigned long long ull;

#define NEXPERTS 64
#define S_MAX    8192
#define ZCHUNK   16384      // bytes per bulk store (= smem zero buffer size)

// static scratch (no allocations allowed)
__device__ int   g_idx[S_MAX];
__device__ float g_gate[S_MAX];
__device__ float g_me_partial[(S_MAX / 64) * NEXPERTS];  // per-tile gate sums
__device__ int   g_cnt[(S_MAX / 64) * NEXPERTS];         // per-tile expert counts
__device__ int   g_base[(S_MAX / 64) * NEXPERTS];        // exclusive prefix per tile
__device__ int   g_rank[S_MAX];                          // rank within tile
__device__ float g_prod[NEXPERTS];                       // me*ce per expert

__device__ __forceinline__ ull pack2(float lo, float hi) {
    ull r; asm("mov.b64 %0, {%1, %2};" : "=l"(r) : "f"(lo), "f"(hi)); return r;
}
__device__ __forceinline__ void ffma2(ull& d, ull a, ull b) {
    asm("fma.rn.f32x2 %0, %1, %2, %0;" : "+l"(d) : "l"(a), "l"(b));
}
__device__ __forceinline__ void fadd2(ull& d, ull a) {
    asm("add.rn.f32x2 %0, %0, %1;" : "+l"(d) : "l"(a));
}
__device__ __forceinline__ float2 unpack2(ull v) {
    float2 r; asm("mov.b64 {%0, %1}, %2;" : "=f"(r.x), "=f"(r.y) : "l"(v)); return r;
}
__device__ __forceinline__ uint32_t smem_u32(const void* p) {
    uint32_t a;
    asm("{ .reg .u64 t; cvta.to.shared.u64 t, %1; cvt.u32.u64 %0, t; }" : "=r"(a) : "l"(p));
    return a;
}
// named barrier for the 8 gemm warps only (TMA warp never joins)
#define GSYNC() asm volatile("bar.sync 1, 256;" ::: "memory")

// ---------------------------------------------------------------------------
// Kernel 1 (warp-specialized, exact R10 zeroing config): 288 threads,
// grid = ngemm (=128) blocks.
//   warps 0-7: gemm+softmax for one 64-token tile (2-way k-split, micro
//     8 tok x 4 exp, FFMA2, named-barrier synced). Epilogue additionally
//     computes per-tile expert counts and per-token rank-in-tile via warp
//     ballots (replaces the separate hist_rank kernel).
//   warp 8: TMA bulk zero-stores over ALL of d_out, chunk-strided across
//     blocks. TMA costs no SM issue slots; this config measured 4.8 TB/s
//     combined traffic (~85% of the practical cap) in R10.
// ---------------------------------------------------------------------------
__global__ __launch_bounds__(288) void gemm_zero_softmax(const float* __restrict__ x,
                                                         const float* __restrict__ wg,
                                                         int D, int S, int ngemm,
                                                         char* __restrict__ zout,
                                                         size_t zbytes) {
    __shared__ __align__(16) float sm[64 * 68];     // As[32][68]+Bs[32][68] -> Ls[64][68]
    __shared__ __align__(16) ull  partial[128][16]; // k-split partial accumulators
    __shared__ __align__(128) float4 zbuf[ZCHUNK / 16];
    __shared__ float sm_m[64], sm_inv[64], red4[4][64];
    __shared__ int   cnt_s[2][64];                  // per-halfwarp expert counts
    float (*As)[68] = (float(*)[68])sm;
    float (*Bs)[68] = (float(*)[68])(sm + 32 * 68);
    float (*Ls)[68] = (float(*)[68])sm;

    const int tid = threadIdx.x;
    const int bid = blockIdx.x;
    const size_t n16 = zbytes & ~(size_t)15;

    if (tid >= 256) {
        // ---------------- TMA zero warp: all of d_out ----------------
        const int lane = tid - 256;
        const float4 z4 = make_float4(0.f, 0.f, 0.f, 0.f);
        for (int i = lane; i < ZCHUNK / 16; i += 32) zbuf[i] = z4;
        asm volatile("fence.proxy.async.shared::cta;" ::: "memory");
        __syncwarp();

        if (lane == 0) {
            const uint32_t saddr = smem_u32(zbuf);
            const size_t nchunk = (n16 + ZCHUNK - 1) / ZCHUNK;
            for (size_t c = bid; c < nchunk; c += gridDim.x) {
                size_t off = c * (size_t)ZCHUNK;
                uint32_t sz = (uint32_t)((n16 - off < ZCHUNK) ? (n16 - off) : ZCHUNK);
                asm volatile(
                    "cp.async.bulk.global.shared::cta.bulk_group [%0], [%1], %2;"
                    :: "l"(zout + off), "r"(saddr), "r"(sz) : "memory");
            }
            asm volatile("cp.async.bulk.commit_group;" ::: "memory");
            asm volatile("cp.async.bulk.wait_group 0;" ::: "memory");
            if (bid == 0) {                        // tail bytes (< 16)
                for (size_t t = n16; t < zbytes; t += 4) *(float*)(zout + t) = 0.f;
            }
        }
        return;   // never touches named barrier 1
    }

    // ---------------- GEMM warps (tid 0..255) ----------------
    const int g    = tid >> 7;         // k-split half
    const int tid2 = tid & 127;
    const int ty   = tid2 >> 4;        // 0..7  -> tokens ty*8 .. ty*8+7
    const int tx   = tid2 & 15;        // 0..15 -> experts tx*4 .. tx*4+3
    const int s0   = bid * 64;

    int rowr[2], k4r[2];
    const float *xp[2], *wp[2];
#pragma unroll
    for (int r = 0; r < 2; ++r) {
        int i = tid + r * 256;
        rowr[r] = i >> 3; k4r[r] = (i & 7) << 2;
        xp[r] = x  + (size_t)(s0 + rowr[r]) * D + k4r[r];
        wp[r] = wg + (size_t)rowr[r] * D + k4r[r];
    }

    ull acc[4][4];
#pragma unroll
    for (int i = 0; i < 4; ++i)
#pragma unroll
        for (int j = 0; j < 4; ++j) acc[i][j] = 0ull;

    float4 pa[2], pb[2];
#pragma unroll
    for (int r = 0; r < 2; ++r) { pa[r] = *(const float4*)(xp[r]); pb[r] = *(const float4*)(wp[r]); }

    for (int kt = 0; kt < D; kt += 32) {
#pragma unroll
        for (int r = 0; r < 2; ++r) {
            int row = rowr[r], k4 = k4r[r];
            As[k4 + 0][row] = pa[r].x; As[k4 + 1][row] = pa[r].y;
            As[k4 + 2][row] = pa[r].z; As[k4 + 3][row] = pa[r].w;
            Bs[k4 + 0][row] = pb[r].x; Bs[k4 + 1][row] = pb[r].y;
            Bs[k4 + 2][row] = pb[r].z; Bs[k4 + 3][row] = pb[r].w;
        }
        GSYNC();
        if (kt + 32 < D) {
#pragma unroll
            for (int r = 0; r < 2; ++r) {
                pa[r] = *(const float4*)(xp[r] + kt + 32);
                pb[r] = *(const float4*)(wp[r] + kt + 32);
            }
        }
#pragma unroll
        for (int k = 0; k < 16; ++k) {
            const int kk = k + g * 16;
            ulonglong2 A0 = *(const ulonglong2*)&As[kk][ty * 8];
            ulonglong2 A1 = *(const ulonglong2*)&As[kk][ty * 8 + 4];
            ull a0 = A0.x, a1 = A0.y, a2 = A1.x, a3 = A1.y;   // 8 tokens (4 pairs)
            float4 bv = *(const float4*)&Bs[kk][tx * 4];
            ull b0 = pack2(bv.x, bv.x), b1 = pack2(bv.y, bv.y);
            ull b2 = pack2(bv.z, bv.z), b3 = pack2(bv.w, bv.w);
            ffma2(acc[0][0], a0, b0); ffma2(acc[0][1], a0, b1);
            ffma2(acc[0][2], a0, b2); ffma2(acc[0][3], a0, b3);
            ffma2(acc[1][0], a1, b0); ffma2(acc[1][1], a1, b1);
            ffma2(acc[1][2], a1, b2); ffma2(acc[1][3], a1, b3);
            ffma2(acc[2][0], a2, b0); ffma2(acc[2][1], a2, b1);
            ffma2(acc[2][2], a2, b2); ffma2(acc[2][3], a2, b3);
            ffma2(acc[3][0], a3, b0); ffma2(acc[3][1], a3, b1);
            ffma2(acc[3][2], a3, b2); ffma2(acc[3][3], a3, b3);
        }
        GSYNC();
    }

    // k-split reduce: half g=1 parks partials in smem, half g=0 accumulates
    if (g == 1) {
#pragma unroll
        for (int i = 0; i < 4; ++i)
#pragma unroll
            for (int j = 0; j < 4; ++j)
                partial[tid2][i * 4 + j] = acc[i][j];
    }
    GSYNC();
    if (g == 0) {
#pragma unroll
        for (int i = 0; i < 4; ++i)
#pragma unroll
            for (int j = 0; j < 4; ++j)
                fadd2(acc[i][j], partial[tid2][i * 4 + j]);
    }
    GSYNC();

    // dump logit tile into smem (As/Bs dead now)
    if (g == 0) {
#pragma unroll
        for (int i = 0; i < 4; ++i) {
            float2 c0 = unpack2(acc[i][0]);
            float2 c1 = unpack2(acc[i][1]);
            float2 c2 = unpack2(acc[i][2]);
            float2 c3 = unpack2(acc[i][3]);
            int t0 = ty * 8 + 2 * i;
            *(float4*)&Ls[t0][tx * 4]     = make_float4(c0.x, c1.x, c2.x, c3.x);
            *(float4*)&Ls[t0 + 1][tx * 4] = make_float4(c0.y, c1.y, c2.y, c3.y);
        }
    }
    if (tid < 128) cnt_s[tid >> 6][tid & 63] = 0;
    GSYNC();

    // per-token softmax + argmax (first max wins = jnp.argmax) + ballot rank
    int ix = 0, inr = 0;
    if (tid < 64) {
        float m = -1e30f;
#pragma unroll 8
        for (int e = 0; e < 64; ++e) {
            float v = Ls[tid][e];
            if (v > m) { m = v; ix = e; }
        }
        float ssum = 0.f;
#pragma unroll 8
        for (int e = 0; e < 64; ++e) ssum += expf(Ls[tid][e] - m);
        float inv = 1.0f / ssum;
        g_idx[s0 + tid]  = ix;
        g_gate[s0 + tid] = inv;
        sm_m[tid] = m; sm_inv[tid] = inv;
        // rank-in-tile via ballot (token order = warp order x lane order)
        const int lane = tid & 31;
        unsigned mk = __match_any_sync(0xffffffffu, ix);
        inr = __popc(mk & ((1u << lane) - 1));
        if (inr == 0) cnt_s[tid >> 5][ix] = __popc(mk);
    }
    GSYNC();
    if (tid < 64) {
        g_rank[s0 + tid] = inr + ((tid >= 32) ? cnt_s[0][ix] : 0);
        g_cnt[(size_t)bid * 64 + tid] = cnt_s[0][tid] + cnt_s[1][tid];
    }
    GSYNC();

    // per-block me partials: me_e += sum_t softmax(l)[t][e]
    {
        const int e = tid & 63, q = tid >> 6;     // q: 0..3, 16 tokens each
        float mp = 0.f;
#pragma unroll
        for (int t = q * 16; t < q * 16 + 16; ++t)
            mp += expf(Ls[t][e] - sm_m[t]) * sm_inv[t];
        red4[q][e] = mp;
    }
    GSYNC();
    if (tid < 64)
        g_me_partial[(size_t)bid * 64 + tid] =
            red4[0][tid] + red4[1][tid] + red4[2][tid] + red4[3][tid];
}

// ---------------------------------------------------------------------------
// Kernel 2: per-expert tile prefix + me reduction (64 blocks, 128 threads).
// Integer Hillis-Steele scan (exact) + fixed-order float tree (deterministic).
// ---------------------------------------------------------------------------
__global__ __launch_bounds__(128) void prefix64(int S, int ntile) {
    __shared__ int   c_s[128];
    __shared__ float red[128];
    const int e = blockIdx.x;
    const int t = threadIdx.x;

    const int orig = (t < ntile) ? g_cnt[(size_t)t * 64 + e] : 0;
    c_s[t] = orig;
    red[t] = (t < ntile) ? g_me_partial[(size_t)t * 64 + e] : 0.f;
    __syncthreads();

    int val = orig;
#pragma unroll
    for (int off = 1; off < 128; off <<= 1) {
        int add = (t >= off) ? c_s[t - off] : 0;
        __syncthreads();
        val += add;
        c_s[t] = val;
        __syncthreads();
    }
    if (t < ntile) g_base[(size_t)t * 64 + e] = val - orig;   // exclusive prefix
    const int total = c_s[127];

#pragma unroll
    for (int o = 64; o; o >>= 1) {
        if (t < o) red[t] += red[t + o];
        __syncthreads();
    }
    if (t == 0) {
        float me = red[0] / (float)S;
        float ce = (float)total / (float)S;   // counts BEFORE capacity drop
        g_prod[e] = me * ce;
    }
}

// ---------------------------------------------------------------------------
// Kernel 3: sparse scatter into the (zeroed) output + l_aux (block 0,
// fixed-order serial sum -> deterministic).
// ---------------------------------------------------------------------------
__global__ void scatter_out(float* __restrict__ out, int S, int C,
                            long long comb_off, long long disp_off, int write_aux) {
    if (blockIdx.x == 0) {
        __shared__ float pr[64];
        if (threadIdx.x < 64) pr[threadIdx.x] = g_prod[threadIdx.x];
        __syncthreads();
        if (threadIdx.x == 0 && write_aux) {
            float sum = 0.f;
            for (int e2 = 0; e2 < 64; ++e2) sum += pr[e2];
            out[0] = sum * (float)NEXPERTS;   // mean(me*ce)*E^2 = sum*E
        }
    }
    int s = blockIdx.x * blockDim.x + threadIdx.x;
    if (s < S) {
        int e = g_idx[s];
        int r = g_base[(size_t)(s >> 6) * 64 + e] + g_rank[s];
        if (r < C) {
            size_t pos = ((size_t)s * NEXPERTS + e) * (size_t)C + r;
            out[(size_t)comb_off + pos] = g_gate[s];
            if (disp_off >= 0)
                out[(size_t)disp_off + pos] = 1.0f;
        }
    }
}

extern "C" void kernel_launch(void* const* d_in, const int* in_sizes, int n_in,
                              void* d_out, int out_size) {
    const float* x  = (const float*)d_in[0];
    const float* wg = (const float*)d_in[1];
    const int D = in_sizes[1] / NEXPERTS;
    const int S = in_sizes[0] / D;
    const int C = (S + NEXPERTS - 1) / NEXPERTS;   // capacity_factor = 1.0
    const size_t SEC = (size_t)S * NEXPERTS * C;
    const size_t osz = (size_t)out_size;

    long long comb = 0, disp = -1; int aux = 0;
    if (osz >= 2 * SEC + 1)      { aux = 1; comb = 1; disp = 1 + (long long)SEC; }
    else if (osz >= 2 * SEC)     { comb = 0; disp = (long long)SEC; }

    const int ngemm = S / 64;   // 128 tiles (fits the 128-wide scan)

    gemm_zero_softmax<<<ngemm, 288>>>(x, wg, D, S, ngemm,
                                      (char*)d_out, osz * sizeof(float));
    prefix64<<<NEXPERTS, 128>>>(S, ngemm);
    scatter_out<<<(S + 255) / 256, 256>>>((float*)d_out, S, C, comb, disp, aux);
}